// round 14
// baseline (speedup 1.0000x reference)
#include <cuda_runtime.h>

#define HW   512
#define NPIX (512*512)

// ---------------- scratch ----------------
__device__ float g_pe1[8*NPIX], g_pe2[8*NPIX];
__device__ float g_ge1[8*NPIX], g_ge2[8*NPIX];
__device__ int   g_tmax[4];
__device__ int   g_vmax[6];
__device__ float g_partial[7680];

#define L2E   14.4269504f
#define HL2E  7.2134752f
#define IL2E  0.069314718f
#define MCL   1048576.f

__device__ __forceinline__ float ex2a(float x){ float r; asm("ex2.approx.ftz.f32 %0, %1;" : "=f"(r) : "f"(x)); return r; }
__device__ __forceinline__ float rcpa(float x){ float r; asm("rcp.approx.ftz.f32 %0, %1;" : "=f"(r) : "f"(x)); return r; }
__device__ __forceinline__ float sigm10(float v, float beta){
    return rcpa(1.f + ex2a((beta - v) * L2E));
}

typedef unsigned long long pf;
__device__ __forceinline__ pf PADD(pf a, pf b){ pf r; asm("add.rn.f32x2 %0, %1, %2;" : "=l"(r) : "l"(a), "l"(b)); return r; }
__device__ __forceinline__ pf PMUL(pf a, pf b){ pf r; asm("mul.rn.f32x2 %0, %1, %2;" : "=l"(r) : "l"(a), "l"(b)); return r; }
__device__ __forceinline__ pf PFMA(pf a, pf b, pf c){ pf r; asm("fma.rn.f32x2 %0, %1, %2, %3;" : "=l"(r) : "l"(a), "l"(b), "l"(c)); return r; }
__device__ __forceinline__ pf PK2(float lo, float hi){ pf r; asm("mov.b64 %0, {%1, %2};" : "=l"(r) : "f"(lo), "f"(hi)); return r; }
__device__ __forceinline__ void UPK(pf a, float& lo, float& hi){ asm("mov.b64 {%0, %1}, %2;" : "=f"(lo), "=f"(hi) : "l"(a)); }

#define C_ONE2  PK2(1.f,1.f)
#define C_TWO2  PK2(2.f,2.f)
#define C_HALF2 PK2(0.5f,0.5f)
#define C_NH2   PK2(-HL2E,-HL2E)

__device__ __forceinline__ void mexp(pf w2, pf& m2, pf& mn2){
    pf u2 = PFMA(w2, C_HALF2, C_NH2);
    float u0,u1; UPK(u2,u0,u1);
    float m0 = ex2a(u0), m1 = ex2a(u1);
    m2  = PK2(m0, m1);
    mn2 = PK2(fminf(m0,MCL), fminf(m1,MCL));
}
__device__ __forceinline__ void npair(pf mnA, pf mnB, pf& Sn){
    pf eA = PMUL(mnA,mnA), eB = PMUL(mnB,mnB);
    pf s  = PADD(eA,eB);
    pf d  = PFMA(eA, eB, PADD(C_ONE2, s));
    pf n  = PADD(C_TWO2, s);
    float d0,d1; UPK(d,d0,d1);
    Sn = PFMA(n, PK2(rcpa(d0),rcpa(d1)), Sn);
}
__device__ __forceinline__ void ipair(pf mA, pf mB, pf ih, pf& Si){
    pf qA = PMUL(mA, ih), qB = PMUL(mB, ih);
    pf a  = PMUL(qA,qA),  b  = PMUL(qB,qB);
    pf s  = PADD(a,b);
    pf p  = PMUL(a,b);
    pf d  = PADD(PADD(C_ONE2,s), p);
    pf n  = PFMA(p, C_TWO2, s);
    float d0,d1; UPK(d,d0,d1);
    Si = PFMA(n, PK2(rcpa(d0),rcpa(d1)), Si);
}
__device__ __forceinline__ void nsingle(pf mn, pf& Sn){
    pf e = PMUL(mn,mn);
    pf d = PADD(C_ONE2, e);
    float d0,d1; UPK(d,d0,d1);
    Sn = PADD(Sn, PK2(rcpa(d0),rcpa(d1)));
}
__device__ __forceinline__ void isingle(pf m, pf ih, pf& Si){
    pf q = PMUL(m, ih);
    pf a = PMUL(q,q);
    pf d = PADD(C_ONE2, a);
    float d0,d1; UPK(d,d0,d1);
    Si = PFMA(a, PK2(rcpa(d0),rcpa(d1)), Si);
}

// ---------------- geometry ----------------
#define SSN 34
#define SSP 35
#define NT  256
#define TS  32
#define PK  21

#define TREE_BODY2                                                                 \
    {   /* K6 */                                                                   \
        pf a0=RW(0,0),b0=RW(0,1),c0_=RW(0,2),d0=RW(0,3),e0=RW(0,4),f0=RW(0,5);     \
        pf a1=RW(1,0),f1=RW(1,5);                                                  \
        pf a2=RW(2,0),f2=RW(2,5);                                                  \
        pf a3=RW(3,0),f3=RW(3,5);                                                  \
        pf a4=RW(4,0),f4=RW(4,5);                                                  \
        pf a5=RW(5,0),b5=RW(5,1),c5=RW(5,2),d5=RW(5,3),e5=RW(5,4),f5=RW(5,5);      \
        pf r0_03=PADD(e0,f0), r0_30=PADD(a0,b0);                                   \
        pf r0_66=PADD(PADD(r0_30,PADD(c0_,d0)),r0_03);                             \
        pf r5_03=PADD(e5,f5), r5_30=PADD(a5,b5);                                   \
        pf r5_66=PADD(PADD(r5_30,PADD(c5,d5)),r5_03), r5_s=PADD(a5,f5);            \
        pf r1_s=PADD(a1,f1), r2_s=PADD(a2,f2), r3_s=PADD(a3,f3), r4_s=PADD(a4,f4); \
        pf t23a=PADD(a2,a3), t123a=PADD(a1,t23a), t234a=PADD(t23a,a4);             \
        pf t23f=PADD(f2,f3), t123f=PADD(f1,t23f), t234f=PADD(t23f,f4);             \
        TERMP(PADD(PADD(r0_03,t123f),PADD(r4_s,r5_66)),                            \
              PADD(PADD(r0_30,t123a),PADD(r4_s,r5_66)), 13)                        \
        TERMP(PADD(PADD(r0_66,r1_s),PADD(t234a,r5_30)),                            \
              PADD(PADD(r0_66,r1_s),PADD(t234f,r5_03)), 13)                        \
        TERMP(PADD(PADD(r0_66,t123a),PADD(a4,r5_66)),                              \
              PADD(PADD(r0_66,t123f),PADD(f4,r5_66)), 16)                          \
        TERMS(PADD(PADD(r0_66,PADD(r1_s,r2_s)),PADD(PADD(r3_s,r4_s),r5_s)), 16)    \
    }                                                                              \
    {   /* K5 */                                                                   \
        pf a1=RW(1,1),b1=RW(1,2),c1=RW(1,3),d1=RW(1,4),e1=RW(1,5);                 \
        pf a2=RW(2,1),e2=RW(2,5);                                                  \
        pf a3=RW(3,1),e3=RW(3,5);                                                  \
        pf a4=RW(4,1),e4=RW(4,5);                                                  \
        pf a5=RW(5,1),b5=RW(5,2),c5=RW(5,3),d5=RW(5,4),e5=RW(5,5);                 \
        pf r1_02=PADD(d1,e1), r1_20=PADD(a1,b1);                                   \
        pf r1_55=PADD(PADD(r1_20,c1),r1_02), r1_s=PADD(a1,e1);                     \
        pf q2=PADD(a2,e2), q3=PADD(a3,e3), q4=PADD(a4,e4);                         \
        pf r5_02=PADD(d5,e5), r5_20=PADD(a5,b5);                                   \
        pf r5_55=PADD(PADD(r5_20,c5),r5_02), r5_s=PADD(a5,e5);                     \
        pf t23a=PADD(a2,a3), t23e=PADD(e2,e3), t234=PADD(PADD(q2,q3),q4);          \
        TERMP(PADD(PADD(r1_02,t23e),PADD(q4,r5_55)),                               \
              PADD(PADD(r1_20,t23a),PADD(q4,r5_55)), 11)                           \
        TERMP(PADD(PADD(r1_55,q2),PADD(PADD(a3,a4),r5_20)),                        \
              PADD(PADD(r1_55,q2),PADD(PADD(e3,e4),r5_02)), 11)                    \
        TERMP(PADD(PADD(r1_55,t23a),PADD(a4,r5_55)),                               \
              PADD(PADD(r1_55,t23e),PADD(e4,r5_55)), 13)                           \
        TERMP(PADD(PADD(r1_55,t234),r5_s),                                         \
              PADD(PADD(r1_s,t234),r5_55), 13)                                     \
    }                                                                              \
    {   /* K4 */                                                                   \
        pf a1=RW(1,1),b1=RW(1,2),c1=RW(1,3),d1=RW(1,4);                            \
        pf a2=RW(2,1),d2=RW(2,4);                                                  \
        pf a3=RW(3,1),d3=RW(3,4);                                                  \
        pf a4=RW(4,1),b4=RW(4,2),c4=RW(4,3),d4=RW(4,4);                            \
        pf r1_01=PADD(c1,d1), r1_10=PADD(a1,b1), r1_44=PADD(r1_01,r1_10), r1_s=PADD(a1,d1); \
        pf q2=PADD(a2,d2), q3=PADD(a3,d3);                                         \
        pf r4_01=PADD(c4,d4), r4_10=PADD(a4,b4), r4_44=PADD(r4_01,r4_10), r4_s=PADD(a4,d4); \
        pf t23=PADD(q2,q3);                                                        \
        TERMP(PADD(PADD(r1_01,d2),PADD(q3,r4_44)),                                 \
              PADD(PADD(r1_10,a2),PADD(q3,r4_44)), 9)                              \
        TERMP(PADD(PADD(r1_44,q2),PADD(d3,r4_01)),                                 \
              PADD(PADD(r1_44,q2),PADD(a3,r4_10)), 9)                              \
        TERMP(PADD(PADD(r1_s,t23),r4_44),                                          \
              PADD(PADD(r1_44,PADD(d2,d3)),r4_44), 10)                             \
        TERMP(PADD(PADD(r1_44,t23),r4_s),                                          \
              PADD(PADD(r1_44,PADD(a2,a3)),r4_44), 10)                             \
    }                                                                              \
    {   /* K3 */                                                                   \
        pf a2=RW(2,2),b2=RW(2,3),c2=RW(2,4);                                       \
        pf a3=RW(3,2),c3=RW(3,4);                                                  \
        pf a4=RW(4,2),b4=RW(4,3),c4=RW(4,4);                                       \
        pf r2_10=PADD(a2,b2), r2_33=PADD(r2_10,c2), r2_s=PADD(a2,c2), r2_01=PADD(b2,c2); \
        pf q3=PADD(a3,c3);                                                         \
        pf r4_10=PADD(a4,b4), r4_33=PADD(r4_10,c4), r4_s=PADD(a4,c4), r4_01=PADD(b4,c4); \
        TERMP(PADD(PADD(r2_33,c3),r4_33), PADD(PADD(r2_33,q3),r4_s), 7)            \
        TERMP(PADD(PADD(r2_33,a3),r4_33), PADD(PADD(r2_s,q3),r4_33), 7)            \
        TERMP(PADD(PADD(r2_01,q3),r4_33), PADD(PADD(r2_33,q3),r4_01), 7)           \
        TERMP(PADD(PADD(r2_33,q3),r4_10), PADD(PADD(r2_10,q3),r4_33), 7)           \
    }

// ---------------- init ----------------
__global__ void init_kernel(){
    int t = threadIdx.x;
    if (t < 4) g_tmax[t] = 0;
    if (t < 6) g_vmax[t] = 0;
}

// ---------------- erosion pass A: 8 px/thread ----------------
// grid (64, 16), k<2: 64*256*2*8 = 262144 px
__global__ __launch_bounds__(256) void erode_max(const float* __restrict__ psrc,
                                                 const float* __restrict__ gsrc,
                                                 int lvl){
    __shared__ float sW[8], sW2[8];
    const int img = blockIdx.y;
    const float* src;
    if (lvl == 1) src = (img < 8) ? psrc + img*NPIX : gsrc + (img-8)*NPIX;
    else          src = (img < 8) ? g_pe1 + img*NPIX : g_ge1 + (img-8)*NPIX;
    const int tid = threadIdx.x;
    float mt = 0.f, mr = 0.f;
#pragma unroll
    for (int k = 0; k < 2; ++k){
        int base = blockIdx.x*4096 + k*2048 + tid*8;
        int y = base >> 9, x = base & 511;
        float4 a  = *(const float4*)(src + base);
        float4 b  = *(const float4*)(src + base + 4);
        float4 ua = (y > 0)    ? *(const float4*)(src + base - HW)     : make_float4(0,0,0,0);
        float4 ub = (y > 0)    ? *(const float4*)(src + base - HW + 4) : make_float4(0,0,0,0);
        float4 da = (y < HW-1) ? *(const float4*)(src + base + HW)     : make_float4(0,0,0,0);
        float4 db = (y < HW-1) ? *(const float4*)(src + base + HW + 4) : make_float4(0,0,0,0);
        float  lf = (x > 0)    ? src[base - 1] : 0.f;
        float  rt = (x < 504)  ? src[base + 8] : 0.f;
        float t0 = ua.x + da.x + lf  + a.y;
        float t1 = ua.y + da.y + a.x + a.z;
        float t2 = ua.z + da.z + a.y + a.w;
        float t3 = ua.w + da.w + a.z + b.x;
        float t4 = ub.x + db.x + a.w + b.y;
        float t5 = ub.y + db.y + b.x + b.z;
        float t6 = ub.z + db.z + b.y + b.w;
        float t7 = ub.w + db.w + b.z + rt;
        mt = fmaxf(mt, fmaxf(fmaxf(fmaxf(t0,t1), fmaxf(t2,t3)),
                             fmaxf(fmaxf(t4,t5), fmaxf(t6,t7))));
        if (lvl == 1){
            mr = fmaxf(mr, fmaxf(fmaxf(a.x,a.y), fmaxf(a.z,a.w)));
            mr = fmaxf(mr, fmaxf(fmaxf(b.x,b.y), fmaxf(b.z,b.w)));
        }
    }
#pragma unroll
    for (int o = 16; o > 0; o >>= 1){
        mt = fmaxf(mt, __shfl_xor_sync(0xffffffffu, mt, o));
        mr = fmaxf(mr, __shfl_xor_sync(0xffffffffu, mr, o));
    }
    if ((tid & 31) == 0){ sW[tid>>5] = mt; sW2[tid>>5] = mr; }
    __syncthreads();
    if (tid == 0){
#pragma unroll
        for (int i = 1; i < 8; ++i){ mt = fmaxf(mt, sW[i]); mr = fmaxf(mr, sW2[i]); }
        atomicMax(&g_tmax[2*(lvl-1) + (img < 8 ? 0 : 1)], __float_as_int(mt));
        if (lvl == 1) atomicMax(&g_vmax[img < 8 ? 0 : 3], __float_as_int(mr));
    }
}

// ---------------- erosion pass B: 8 px/thread ----------------
__global__ __launch_bounds__(256) void erode_finish(const float* __restrict__ psrc,
                                                    const float* __restrict__ gsrc,
                                                    int lvl){
    __shared__ float sW[8];
    const int img = blockIdx.y;
    const float* src;
    float* dst;
    if (lvl == 1){ src = (img < 8) ? psrc + img*NPIX : gsrc + (img-8)*NPIX;
                   dst = (img < 8) ? g_pe1 + img*NPIX : g_ge1 + (img-8)*NPIX; }
    else         { src = (img < 8) ? g_pe1 + img*NPIX : g_ge1 + (img-8)*NPIX;
                   dst = (img < 8) ? g_pe2 + img*NPIX : g_ge2 + (img-8)*NPIX; }
    const int tid = threadIdx.x;
    const float tmax = __int_as_float(g_tmax[2*(lvl-1) + (img < 8 ? 0 : 1)]);
    const float inv = __frcp_rn(tmax + 1e-8f);
    float mv = 0.f;
#pragma unroll
    for (int k = 0; k < 2; ++k){
        int base = blockIdx.x*4096 + k*2048 + tid*8;
        int y = base >> 9, x = base & 511;
        float4 a  = *(const float4*)(src + base);
        float4 b  = *(const float4*)(src + base + 4);
        float4 ua = (y > 0)    ? *(const float4*)(src + base - HW)     : make_float4(0,0,0,0);
        float4 ub = (y > 0)    ? *(const float4*)(src + base - HW + 4) : make_float4(0,0,0,0);
        float4 da = (y < HW-1) ? *(const float4*)(src + base + HW)     : make_float4(0,0,0,0);
        float4 db = (y < HW-1) ? *(const float4*)(src + base + HW + 4) : make_float4(0,0,0,0);
        float  lf = (x > 0)    ? src[base - 1] : 0.f;
        float  rt = (x < 504)  ? src[base + 8] : 0.f;
        float4 va, vb;
        va.x = sigm10((ua.x + da.x + lf  + a.y) * inv, 0.7f);
        va.y = sigm10((ua.y + da.y + a.x + a.z) * inv, 0.7f);
        va.z = sigm10((ua.z + da.z + a.y + a.w) * inv, 0.7f);
        va.w = sigm10((ua.w + da.w + a.z + b.x) * inv, 0.7f);
        vb.x = sigm10((ub.x + db.x + a.w + b.y) * inv, 0.7f);
        vb.y = sigm10((ub.y + db.y + b.x + b.z) * inv, 0.7f);
        vb.z = sigm10((ub.z + db.z + b.y + b.w) * inv, 0.7f);
        vb.w = sigm10((ub.w + db.w + b.z + rt ) * inv, 0.7f);
        *(float4*)(dst + base)     = va;
        *(float4*)(dst + base + 4) = vb;
        mv = fmaxf(mv, fmaxf(fmaxf(fmaxf(va.x,va.y), fmaxf(va.z,va.w)),
                             fmaxf(fmaxf(vb.x,vb.y), fmaxf(vb.z,vb.w))));
    }
#pragma unroll
    for (int o = 16; o > 0; o >>= 1) mv = fmaxf(mv, __shfl_xor_sync(0xffffffffu, mv, o));
    if ((tid & 31) == 0) sW[tid >> 5] = mv;
    __syncthreads();
    if (tid == 0){
#pragma unroll
        for (int i = 1; i < 8; ++i) mv = fmaxf(mv, sW[i]);
        atomicMax(&g_vmax[(img < 8 ? 0 : 3) + lvl], __float_as_int(mv));
    }
}

// ---------------- unified cp kernel: interior branch + edge branch ----------------
// grid 7584 x NT=256.  bid<4704: interior;  else edge. (byte-identical to R13)
__global__ __launch_bounds__(NT, 3) void cp_all_kernel(const float* __restrict__ pred0,
                                                       const float* __restrict__ gt0){
    __shared__ pf    fA[39*PK];
    __shared__ pf    fB[39*PK];
    __shared__ float sS[2][SSN*SSP];
    __shared__ float sW[8];
    const int tid = threadIdx.x;
    const int bid = blockIdx.x;

    if (bid < 4704){
        const int z   = bid / 196;
        const int rem = bid - z*196;
        const int by  = rem / 14, bx = rem - by*14;
        const int level = z >> 3;
        const int b     = z & 7;
        const int oy = (by + 1) * TS, ox = (bx + 1) * TS;

        float cp[2][2][4];
        for (int ts = 0; ts < 2; ++ts){
            const float* base = (ts == 0)
                ? (level == 0 ? pred0 : (level == 1 ? g_pe1 : g_pe2))
                : (level == 0 ? gt0   : (level == 1 ? g_ge1 : g_ge2));
            const float* src = base + b*NPIX;
            const float vmax = __int_as_float(g_vmax[(ts ? 3 : 0) + level]);
            const float vk = HL2E * vmax;
            const float ih7f  = exp2f(L2E - 7.f*vk);
            const float ih9f  = exp2f(L2E - 9.f*vk);
            const float ih10f = exp2f(L2E - 10.f*vk);
            const float ih11f = exp2f(L2E - 11.f*vk);
            const float ih13f = exp2f(L2E - 13.f*vk);
            const float ih16f = exp2f(L2E - 16.f*vk);
            const pf IH7  = PK2(ih7f,ih7f),   IH9  = PK2(ih9f,ih9f);
            const pf IH10 = PK2(ih10f,ih10f), IH11 = PK2(ih11f,ih11f);
            const pf IH13 = PK2(ih13f,ih13f), IH16 = PK2(ih16f,ih16f);

            float* A = (float*)fA; float* B = (float*)fB;
            for (int i = tid; i < 39*39; i += NT){
                int a = i / 39, c = i - a*39;
                float v = src[(oy - 4 + a)*HW + (ox - 4 + c)] * L2E;
                A[(c*PK + (a >> 1))*2 + (a & 1)] = v;
                if (a & 1)       B[(c*PK + (a >> 1))*2]         = v;
                else if (a >= 2) B[(c*PK + (a >> 1) - 1)*2 + 1] = v;
            }
            __syncthreads();

            for (int idx = tid; idx < 34*17; idx += NT){
                int p = idx / 34, x = idx - p*34;
#define RW(r,c) ( ((r) & 1) ? fB[(x+(c))*PK + p + ((r)>>1)] : fA[(x+(c))*PK + p + ((r)>>1)] )
#define TERMP(eA,eB,k) { pf mA,mnA,mB,mnB; mexp((eA),mA,mnA); mexp((eB),mB,mnB); \
                         npair(mnA,mnB,Sn); ipair(mA,mB,IH##k,Si); }
#define TERMS(e,k)     { pf m,mn; mexp((e),m,mn); nsingle(mn,Sn); isingle(m,IH##k,Si); }
                pf Sn = 0ull, Si = 0ull;
                TREE_BODY2
                float S0n,S1n,S0i,S1i; UPK(Sn,S0n,S1n); UPK(Si,S0i,S1i);
                float w0,w1; UPK(RW(3,3), w0, w1);
#undef TERMP
#undef TERMS
#undef RW
                float c00 = w0 * IL2E, c01 = w1 * IL2E;
                int sy = 2*p;
                sS[0][sy*SSP + x]     = sigm10(c00*S0n, 0.5f);
                sS[0][(sy+1)*SSP + x] = sigm10(c01*S1n, 0.5f);
                sS[1][sy*SSP + x]     = sigm10((vmax - c00)*S0i, 0.5f);
                sS[1][(sy+1)*SSP + x] = sigm10((vmax - c01)*S1i, 0.5f);
            }
            __syncthreads();

            for (int idx = tid, j = 0; idx < 2048; idx += NT, ++j){
                int v = idx >> 10, r = idx & 1023;
                int ly = r >> 5, lx = r & 31;
                float acc = 0.f;
#pragma unroll
                for (int dy = 0; dy < 3; ++dy)
#pragma unroll
                    for (int dx = 0; dx < 3; ++dx)
                        acc += sS[v][(ly+dy)*SSP + lx + dx];
                acc = fminf(fmaxf(acc, 0.f), 1.f);
                cp[ts][j >> 2][j & 3] = acc;
            }
            __syncthreads();
        }

        float local = 0.f;
#pragma unroll
        for (int v = 0; v < 2; ++v)
#pragma unroll
        for (int q = 0; q < 4; ++q){
            float d = cp[0][v][q] - cp[1][v][q];
            local += d*d;
        }
#pragma unroll
        for (int o = 16; o > 0; o >>= 1) local += __shfl_xor_sync(0xffffffffu, local, o);
        if ((tid & 31) == 0) sW[tid >> 5] = local;
        __syncthreads();
        if (tid == 0){
            float s = sW[0];
#pragma unroll
            for (int i = 1; i < 8; ++i) s += sW[i];
            g_partial[bid] = s;
        }
    } else {
        const int e  = bid - 4704;
        const int z  = e / 60;
        const int t  = e - z*60;
        const int pt = z >> 3;
        const int b  = z & 7;
        const int level = pt >> 1;
        const int inv   = pt & 1;
        int bx, by;
        if      (t < 16){ bx = t;      by = 0;      }
        else if (t < 32){ bx = t - 16; by = 15;     }
        else if (t < 46){ bx = 0;      by = t - 31; }
        else            { bx = 15;     by = t - 45; }
        const int oy = by * TS, ox = bx * TS;

        float cp[2][4];
        for (int ts = 0; ts < 2; ++ts){
            const float* base = (ts == 0)
                ? (level == 0 ? pred0 : (level == 1 ? g_pe1 : g_pe2))
                : (level == 0 ? gt0   : (level == 1 ? g_ge1 : g_ge2));
            const float* src = base + b*NPIX;
            float vmax = inv ? __int_as_float(g_vmax[(ts ? 3 : 0) + level]) : 0.f;

            float* A = (float*)fA; float* B = (float*)fB;
            for (int i = tid; i < 39*39; i += NT){
                int a = i / 39, c = i - a*39;
                int qy = oy - 4 + a, qx = ox - 4 + c;
                float v;
                if (qy < -1 || qy > HW || qx < -1 || qx > HW) v = 0.f;
                else if (qy == -1 || qy == HW || qx == -1 || qx == HW) v = L2E;
                else { float u = src[qy*HW + qx]; v = (inv ? vmax - u : u) * L2E; }
                A[(c*PK + (a >> 1))*2 + (a & 1)] = v;
                if (a & 1)       B[(c*PK + (a >> 1))*2]         = v;
                else if (a >= 2) B[(c*PK + (a >> 1) - 1)*2 + 1] = v;
            }
            __syncthreads();

            for (int idx = tid; idx < 34*17; idx += NT){
                int p = idx / 34, x = idx - p*34;
#define RW(r,c) ( ((r) & 1) ? fB[(x+(c))*PK + p + ((r)>>1)] : fA[(x+(c))*PK + p + ((r)>>1)] )
#define TERMP(eA,eB,k) { pf mA,mnA,mB,mnB; mexp((eA),mA,mnA); mexp((eB),mB,mnB); \
                         npair(mnA,mnB,Sn); }
#define TERMS(e,k)     { pf m,mn; mexp((e),m,mn); nsingle(mn,Sn); }
                pf Sn = 0ull;
                TREE_BODY2
                float S0,S1; UPK(Sn,S0,S1);
                float w0,w1; UPK(RW(3,3), w0, w1);
#undef TERMP
#undef TERMS
#undef RW
                float c00 = w0 * IL2E, c01 = w1 * IL2E;
                int sy = 2*p;
                int gy0 = oy + sy - 1, gx = ox + x - 1;
                float s0 = sigm10(c00*S0, 0.5f);
                float s1 = sigm10(c01*S1, 0.5f);
                bool okx = ((unsigned)gx < HW);
                if (!okx || (unsigned)gy0     >= HW) s0 = 0.f;
                if (!okx || (unsigned)(gy0+1) >= HW) s1 = 0.f;
                sS[0][sy*SSP + x]     = s0;
                sS[0][(sy+1)*SSP + x] = s1;
            }
            __syncthreads();

#pragma unroll
            for (int q = 0; q < 4; ++q){
                int ly = (tid >> 5) + q*8, lx = tid & 31;
                float acc = 0.f;
#pragma unroll
                for (int dy = 0; dy < 3; ++dy)
#pragma unroll
                    for (int dx = 0; dx < 3; ++dx)
                        acc += sS[0][(ly+dy)*SSP + lx + dx];
                cp[ts][q] = fminf(fmaxf(acc, 0.f), 1.f);
            }
            __syncthreads();
        }

        float local = 0.f;
#pragma unroll
        for (int q = 0; q < 4; ++q){
            float d = cp[0][q] - cp[1][q];
            local += d*d;
        }
#pragma unroll
        for (int o = 16; o > 0; o >>= 1) local += __shfl_xor_sync(0xffffffffu, local, o);
        if ((tid & 31) == 0) sW[tid >> 5] = local;
        __syncthreads();
        if (tid == 0){
            float s = sW[0];
#pragma unroll
            for (int i = 1; i < 8; ++i) s += sW[i];
            g_partial[bid] = s;
        }
    }
}

// ---------------- deterministic final reduction ----------------
__global__ __launch_bounds__(256) void final_kernel(float* out){
    __shared__ double sh[256];
    double a = 0.0;
    for (int i = threadIdx.x; i < 7584; i += 256) a += (double)g_partial[i];
    sh[threadIdx.x] = a; __syncthreads();
    for (int o = 128; o > 0; o >>= 1){
        if (threadIdx.x < o) sh[threadIdx.x] += sh[threadIdx.x+o];
        __syncthreads();
    }
    if (threadIdx.x == 0) out[0] = (float)(sh[0] * 0.125);
}

// ---------------- launch ----------------
extern "C" void kernel_launch(void* const* d_in, const int* in_sizes, int n_in,
                              void* d_out, int out_size){
    const float* pred = (const float*)d_in[0];
    const float* gt   = (const float*)d_in[1];
    float* out = (float*)d_out;
    (void)in_sizes; (void)n_in; (void)out_size;

    init_kernel<<<1, 32>>>();
    erode_max   <<<dim3(64, 16), 256>>>(pred, gt, 1);
    erode_finish<<<dim3(64, 16), 256>>>(pred, gt, 1);
    erode_max   <<<dim3(64, 16), 256>>>(pred, gt, 2);
    erode_finish<<<dim3(64, 16), 256>>>(pred, gt, 2);
    cp_all_kernel<<<7584, NT>>>(pred, gt);
    final_kernel<<<1, 256>>>(out);
}

// round 16
// speedup vs baseline: 1.0493x; 1.0493x over previous
#include <cuda_runtime.h>

#define HW   512
#define NPIX (512*512)

// ---------------- scratch ----------------
__device__ float g_pe1[8*NPIX], g_pe2[8*NPIX];
__device__ float g_ge1[8*NPIX], g_ge2[8*NPIX];
__device__ int   g_tmax[4];
__device__ int   g_vmax[6];
__device__ float g_partial[7680];

#define L2E   14.4269504f
#define HL2E  7.2134752f
#define IL2E  0.069314718f
#define MCL   1048576.f

__device__ __forceinline__ float ex2a(float x){ float r; asm("ex2.approx.ftz.f32 %0, %1;" : "=f"(r) : "f"(x)); return r; }
__device__ __forceinline__ float rcpa(float x){ float r; asm("rcp.approx.ftz.f32 %0, %1;" : "=f"(r) : "f"(x)); return r; }
__device__ __forceinline__ float sigm10(float v, float beta){
    return rcpa(1.f + ex2a((beta - v) * L2E));
}

typedef unsigned long long pf;
__device__ __forceinline__ pf PADD(pf a, pf b){ pf r; asm("add.rn.f32x2 %0, %1, %2;" : "=l"(r) : "l"(a), "l"(b)); return r; }
__device__ __forceinline__ pf PMUL(pf a, pf b){ pf r; asm("mul.rn.f32x2 %0, %1, %2;" : "=l"(r) : "l"(a), "l"(b)); return r; }
__device__ __forceinline__ pf PFMA(pf a, pf b, pf c){ pf r; asm("fma.rn.f32x2 %0, %1, %2, %3;" : "=l"(r) : "l"(a), "l"(b), "l"(c)); return r; }
__device__ __forceinline__ pf PK2(float lo, float hi){ pf r; asm("mov.b64 %0, {%1, %2};" : "=l"(r) : "f"(lo), "f"(hi)); return r; }
__device__ __forceinline__ void UPK(pf a, float& lo, float& hi){ asm("mov.b64 {%0, %1}, %2;" : "=f"(lo), "=f"(hi) : "l"(a)); }

#define C_ONE2  PK2(1.f,1.f)
#define C_TWO2  PK2(2.f,2.f)
#define C_HALF2 PK2(0.5f,0.5f)
#define C_NH2   PK2(-HL2E,-HL2E)

__device__ __forceinline__ void mexp(pf w2, pf& m2, pf& mn2){
    pf u2 = PFMA(w2, C_HALF2, C_NH2);
    float u0,u1; UPK(u2,u0,u1);
    float m0 = ex2a(u0), m1 = ex2a(u1);
    m2  = PK2(m0, m1);
    mn2 = PK2(fminf(m0,MCL), fminf(m1,MCL));
}
__device__ __forceinline__ void npair(pf mnA, pf mnB, pf& Sn){
    pf eA = PMUL(mnA,mnA), eB = PMUL(mnB,mnB);
    pf s  = PADD(eA,eB);
    pf d  = PFMA(eA, eB, PADD(C_ONE2, s));
    pf n  = PADD(C_TWO2, s);
    float d0,d1; UPK(d,d0,d1);
    Sn = PFMA(n, PK2(rcpa(d0),rcpa(d1)), Sn);
}
__device__ __forceinline__ void ipair(pf mA, pf mB, pf ih, pf& Si){
    pf qA = PMUL(mA, ih), qB = PMUL(mB, ih);
    pf a  = PMUL(qA,qA),  b  = PMUL(qB,qB);
    pf s  = PADD(a,b);
    pf p  = PMUL(a,b);
    pf d  = PADD(PADD(C_ONE2,s), p);
    pf n  = PFMA(p, C_TWO2, s);
    float d0,d1; UPK(d,d0,d1);
    Si = PFMA(n, PK2(rcpa(d0),rcpa(d1)), Si);
}
__device__ __forceinline__ void nsingle(pf mn, pf& Sn){
    pf e = PMUL(mn,mn);
    pf d = PADD(C_ONE2, e);
    float d0,d1; UPK(d,d0,d1);
    Sn = PADD(Sn, PK2(rcpa(d0),rcpa(d1)));
}
__device__ __forceinline__ void isingle(pf m, pf ih, pf& Si){
    pf q = PMUL(m, ih);
    pf a = PMUL(q,q);
    pf d = PADD(C_ONE2, a);
    float d0,d1; UPK(d,d0,d1);
    Si = PFMA(a, PK2(rcpa(d0),rcpa(d1)), Si);
}

// ---------------- geometry ----------------
#define SSN 34
#define SSP 35
#define NT  256
#define TS  32
#define PK  21

#define TREE_BODY2                                                                 \
    {   /* K6 */                                                                   \
        pf a0=RW(0,0),b0=RW(0,1),c0_=RW(0,2),d0=RW(0,3),e0=RW(0,4),f0=RW(0,5);     \
        pf a1=RW(1,0),f1=RW(1,5);                                                  \
        pf a2=RW(2,0),f2=RW(2,5);                                                  \
        pf a3=RW(3,0),f3=RW(3,5);                                                  \
        pf a4=RW(4,0),f4=RW(4,5);                                                  \
        pf a5=RW(5,0),b5=RW(5,1),c5=RW(5,2),d5=RW(5,3),e5=RW(5,4),f5=RW(5,5);      \
        pf r0_03=PADD(e0,f0), r0_30=PADD(a0,b0);                                   \
        pf r0_66=PADD(PADD(r0_30,PADD(c0_,d0)),r0_03);                             \
        pf r5_03=PADD(e5,f5), r5_30=PADD(a5,b5);                                   \
        pf r5_66=PADD(PADD(r5_30,PADD(c5,d5)),r5_03), r5_s=PADD(a5,f5);            \
        pf r1_s=PADD(a1,f1), r2_s=PADD(a2,f2), r3_s=PADD(a3,f3), r4_s=PADD(a4,f4); \
        pf t23a=PADD(a2,a3), t123a=PADD(a1,t23a), t234a=PADD(t23a,a4);             \
        pf t23f=PADD(f2,f3), t123f=PADD(f1,t23f), t234f=PADD(t23f,f4);             \
        TERMP(PADD(PADD(r0_03,t123f),PADD(r4_s,r5_66)),                            \
              PADD(PADD(r0_30,t123a),PADD(r4_s,r5_66)), 13)                        \
        TERMP(PADD(PADD(r0_66,r1_s),PADD(t234a,r5_30)),                            \
              PADD(PADD(r0_66,r1_s),PADD(t234f,r5_03)), 13)                        \
        TERMP(PADD(PADD(r0_66,t123a),PADD(a4,r5_66)),                              \
              PADD(PADD(r0_66,t123f),PADD(f4,r5_66)), 16)                          \
        TERMS(PADD(PADD(r0_66,PADD(r1_s,r2_s)),PADD(PADD(r3_s,r4_s),r5_s)), 16)    \
    }                                                                              \
    {   /* K5 */                                                                   \
        pf a1=RW(1,1),b1=RW(1,2),c1=RW(1,3),d1=RW(1,4),e1=RW(1,5);                 \
        pf a2=RW(2,1),e2=RW(2,5);                                                  \
        pf a3=RW(3,1),e3=RW(3,5);                                                  \
        pf a4=RW(4,1),e4=RW(4,5);                                                  \
        pf a5=RW(5,1),b5=RW(5,2),c5=RW(5,3),d5=RW(5,4),e5=RW(5,5);                 \
        pf r1_02=PADD(d1,e1), r1_20=PADD(a1,b1);                                   \
        pf r1_55=PADD(PADD(r1_20,c1),r1_02), r1_s=PADD(a1,e1);                     \
        pf q2=PADD(a2,e2), q3=PADD(a3,e3), q4=PADD(a4,e4);                         \
        pf r5_02=PADD(d5,e5), r5_20=PADD(a5,b5);                                   \
        pf r5_55=PADD(PADD(r5_20,c5),r5_02), r5_s=PADD(a5,e5);                     \
        pf t23a=PADD(a2,a3), t23e=PADD(e2,e3), t234=PADD(PADD(q2,q3),q4);          \
        TERMP(PADD(PADD(r1_02,t23e),PADD(q4,r5_55)),                               \
              PADD(PADD(r1_20,t23a),PADD(q4,r5_55)), 11)                           \
        TERMP(PADD(PADD(r1_55,q2),PADD(PADD(a3,a4),r5_20)),                        \
              PADD(PADD(r1_55,q2),PADD(PADD(e3,e4),r5_02)), 11)                    \
        TERMP(PADD(PADD(r1_55,t23a),PADD(a4,r5_55)),                               \
              PADD(PADD(r1_55,t23e),PADD(e4,r5_55)), 13)                           \
        TERMP(PADD(PADD(r1_55,t234),r5_s),                                         \
              PADD(PADD(r1_s,t234),r5_55), 13)                                     \
    }                                                                              \
    {   /* K4 */                                                                   \
        pf a1=RW(1,1),b1=RW(1,2),c1=RW(1,3),d1=RW(1,4);                            \
        pf a2=RW(2,1),d2=RW(2,4);                                                  \
        pf a3=RW(3,1),d3=RW(3,4);                                                  \
        pf a4=RW(4,1),b4=RW(4,2),c4=RW(4,3),d4=RW(4,4);                            \
        pf r1_01=PADD(c1,d1), r1_10=PADD(a1,b1), r1_44=PADD(r1_01,r1_10), r1_s=PADD(a1,d1); \
        pf q2=PADD(a2,d2), q3=PADD(a3,d3);                                         \
        pf r4_01=PADD(c4,d4), r4_10=PADD(a4,b4), r4_44=PADD(r4_01,r4_10), r4_s=PADD(a4,d4); \
        pf t23=PADD(q2,q3);                                                        \
        TERMP(PADD(PADD(r1_01,d2),PADD(q3,r4_44)),                                 \
              PADD(PADD(r1_10,a2),PADD(q3,r4_44)), 9)                              \
        TERMP(PADD(PADD(r1_44,q2),PADD(d3,r4_01)),                                 \
              PADD(PADD(r1_44,q2),PADD(a3,r4_10)), 9)                              \
        TERMP(PADD(PADD(r1_s,t23),r4_44),                                          \
              PADD(PADD(r1_44,PADD(d2,d3)),r4_44), 10)                             \
        TERMP(PADD(PADD(r1_44,t23),r4_s),                                          \
              PADD(PADD(r1_44,PADD(a2,a3)),r4_44), 10)                             \
    }                                                                              \
    {   /* K3 */                                                                   \
        pf a2=RW(2,2),b2=RW(2,3),c2=RW(2,4);                                       \
        pf a3=RW(3,2),c3=RW(3,4);                                                  \
        pf a4=RW(4,2),b4=RW(4,3),c4=RW(4,4);                                       \
        pf r2_10=PADD(a2,b2), r2_33=PADD(r2_10,c2), r2_s=PADD(a2,c2), r2_01=PADD(b2,c2); \
        pf q3=PADD(a3,c3);                                                         \
        pf r4_10=PADD(a4,b4), r4_33=PADD(r4_10,c4), r4_s=PADD(a4,c4), r4_01=PADD(b4,c4); \
        TERMP(PADD(PADD(r2_33,c3),r4_33), PADD(PADD(r2_33,q3),r4_s), 7)            \
        TERMP(PADD(PADD(r2_33,a3),r4_33), PADD(PADD(r2_s,q3),r4_33), 7)            \
        TERMP(PADD(PADD(r2_01,q3),r4_33), PADD(PADD(r2_33,q3),r4_01), 7)           \
        TERMP(PADD(PADD(r2_33,q3),r4_10), PADD(PADD(r2_10,q3),r4_33), 7)           \
    }

// ---------------- init ----------------
__global__ void init_kernel(){
    int t = threadIdx.x;
    if (t < 4) g_tmax[t] = 0;
    if (t < 6) g_vmax[t] = 0;
}

// ---------------- erosion pass A: 4 px/thread (templated level) ----------------
template<int LVL>
__global__ __launch_bounds__(256) void erode_max(const float* __restrict__ psrc,
                                                 const float* __restrict__ gsrc){
    __shared__ float sW[8], sW2[8];
    const int img = blockIdx.y;
    const float* src;
    if (LVL == 1) src = (img < 8) ? psrc + img*NPIX : gsrc + (img-8)*NPIX;
    else          src = (img < 8) ? g_pe1 + img*NPIX : g_ge1 + (img-8)*NPIX;
    const int tid = threadIdx.x;
    float mt = 0.f, mr = 0.f;
#pragma unroll
    for (int k = 0; k < 4; ++k){
        int base = blockIdx.x*4096 + k*1024 + tid*4;
        int y = base >> 9, x = base & 511;
        float4 mid = *(const float4*)(src + base);
        float4 up  = (y > 0)    ? *(const float4*)(src + base - HW) : make_float4(0,0,0,0);
        float4 dn  = (y < HW-1) ? *(const float4*)(src + base + HW) : make_float4(0,0,0,0);
        float  lf  = (x > 0)    ? src[base - 1] : 0.f;
        float  rt  = (x < 508)  ? src[base + 4] : 0.f;
        float t0 = up.x + dn.x + lf    + mid.y;
        float t1 = up.y + dn.y + mid.x + mid.z;
        float t2 = up.z + dn.z + mid.y + mid.w;
        float t3 = up.w + dn.w + mid.z + rt;
        mt = fmaxf(mt, fmaxf(fmaxf(t0,t1), fmaxf(t2,t3)));
        if (LVL == 1) mr = fmaxf(mr, fmaxf(fmaxf(mid.x,mid.y), fmaxf(mid.z,mid.w)));
    }
#pragma unroll
    for (int o = 16; o > 0; o >>= 1){
        mt = fmaxf(mt, __shfl_xor_sync(0xffffffffu, mt, o));
        if (LVL == 1) mr = fmaxf(mr, __shfl_xor_sync(0xffffffffu, mr, o));
    }
    if ((tid & 31) == 0){ sW[tid>>5] = mt; sW2[tid>>5] = mr; }
    __syncthreads();
    if (tid == 0){
#pragma unroll
        for (int i = 1; i < 8; ++i){ mt = fmaxf(mt, sW[i]); mr = fmaxf(mr, sW2[i]); }
        atomicMax(&g_tmax[2*(LVL-1) + (img < 8 ? 0 : 1)], __float_as_int(mt));
        if (LVL == 1) atomicMax(&g_vmax[img < 8 ? 0 : 3], __float_as_int(mr));
    }
}

// ---------------- erosion pass B: 4 px/thread (templated level) ----------------
template<int LVL>
__global__ __launch_bounds__(256) void erode_finish(const float* __restrict__ psrc,
                                                    const float* __restrict__ gsrc){
    __shared__ float sW[8];
    const int img = blockIdx.y;
    const float* src;
    float* dst;
    if (LVL == 1){ src = (img < 8) ? psrc + img*NPIX : gsrc + (img-8)*NPIX;
                   dst = (img < 8) ? g_pe1 + img*NPIX : g_ge1 + (img-8)*NPIX; }
    else         { src = (img < 8) ? g_pe1 + img*NPIX : g_ge1 + (img-8)*NPIX;
                   dst = (img < 8) ? g_pe2 + img*NPIX : g_ge2 + (img-8)*NPIX; }
    const int tid = threadIdx.x;
    const float tmax = __int_as_float(g_tmax[2*(LVL-1) + (img < 8 ? 0 : 1)]);
    const float inv = __frcp_rn(tmax + 1e-8f);
    float mv = 0.f;
#pragma unroll
    for (int k = 0; k < 4; ++k){
        int base = blockIdx.x*4096 + k*1024 + tid*4;
        int y = base >> 9, x = base & 511;
        float4 mid = *(const float4*)(src + base);
        float4 up  = (y > 0)    ? *(const float4*)(src + base - HW) : make_float4(0,0,0,0);
        float4 dn  = (y < HW-1) ? *(const float4*)(src + base + HW) : make_float4(0,0,0,0);
        float  lf  = (x > 0)    ? src[base - 1] : 0.f;
        float  rt  = (x < 508)  ? src[base + 4] : 0.f;
        float4 v;
        v.x = sigm10((up.x + dn.x + lf    + mid.y) * inv, 0.7f);
        v.y = sigm10((up.y + dn.y + mid.x + mid.z) * inv, 0.7f);
        v.z = sigm10((up.z + dn.z + mid.y + mid.w) * inv, 0.7f);
        v.w = sigm10((up.w + dn.w + mid.z + rt   ) * inv, 0.7f);
        *(float4*)(dst + base) = v;
        mv = fmaxf(mv, fmaxf(fmaxf(v.x,v.y), fmaxf(v.z,v.w)));
    }
#pragma unroll
    for (int o = 16; o > 0; o >>= 1) mv = fmaxf(mv, __shfl_xor_sync(0xffffffffu, mv, o));
    if ((tid & 31) == 0) sW[tid >> 5] = mv;
    __syncthreads();
    if (tid == 0){
#pragma unroll
        for (int i = 1; i < 8; ++i) mv = fmaxf(mv, sW[i]);
        atomicMax(&g_vmax[(img < 8 ? 0 : 3) + LVL], __float_as_int(mv));
    }
}

// ---------------- unified cp kernel: interior branch + edge branch ----------------
// grid 7584 x NT=256.  bid<4704: interior;  else edge. (byte-identical to R13)
__global__ __launch_bounds__(NT, 3) void cp_all_kernel(const float* __restrict__ pred0,
                                                       const float* __restrict__ gt0){
    __shared__ pf    fA[39*PK];
    __shared__ pf    fB[39*PK];
    __shared__ float sS[2][SSN*SSP];
    __shared__ float sW[8];
    const int tid = threadIdx.x;
    const int bid = blockIdx.x;

    if (bid < 4704){
        const int z   = bid / 196;
        const int rem = bid - z*196;
        const int by  = rem / 14, bx = rem - by*14;
        const int level = z >> 3;
        const int b     = z & 7;
        const int oy = (by + 1) * TS, ox = (bx + 1) * TS;

        float cp[2][2][4];
        for (int ts = 0; ts < 2; ++ts){
            const float* base = (ts == 0)
                ? (level == 0 ? pred0 : (level == 1 ? g_pe1 : g_pe2))
                : (level == 0 ? gt0   : (level == 1 ? g_ge1 : g_ge2));
            const float* src = base + b*NPIX;
            const float vmax = __int_as_float(g_vmax[(ts ? 3 : 0) + level]);
            const float vk = HL2E * vmax;
            const float ih7f  = exp2f(L2E - 7.f*vk);
            const float ih9f  = exp2f(L2E - 9.f*vk);
            const float ih10f = exp2f(L2E - 10.f*vk);
            const float ih11f = exp2f(L2E - 11.f*vk);
            const float ih13f = exp2f(L2E - 13.f*vk);
            const float ih16f = exp2f(L2E - 16.f*vk);
            const pf IH7  = PK2(ih7f,ih7f),   IH9  = PK2(ih9f,ih9f);
            const pf IH10 = PK2(ih10f,ih10f), IH11 = PK2(ih11f,ih11f);
            const pf IH13 = PK2(ih13f,ih13f), IH16 = PK2(ih16f,ih16f);

            float* A = (float*)fA; float* B = (float*)fB;
            for (int i = tid; i < 39*39; i += NT){
                int a = i / 39, c = i - a*39;
                float v = src[(oy - 4 + a)*HW + (ox - 4 + c)] * L2E;
                A[(c*PK + (a >> 1))*2 + (a & 1)] = v;
                if (a & 1)       B[(c*PK + (a >> 1))*2]         = v;
                else if (a >= 2) B[(c*PK + (a >> 1) - 1)*2 + 1] = v;
            }
            __syncthreads();

            for (int idx = tid; idx < 34*17; idx += NT){
                int p = idx / 34, x = idx - p*34;
#define RW(r,c) ( ((r) & 1) ? fB[(x+(c))*PK + p + ((r)>>1)] : fA[(x+(c))*PK + p + ((r)>>1)] )
#define TERMP(eA,eB,k) { pf mA,mnA,mB,mnB; mexp((eA),mA,mnA); mexp((eB),mB,mnB); \
                         npair(mnA,mnB,Sn); ipair(mA,mB,IH##k,Si); }
#define TERMS(e,k)     { pf m,mn; mexp((e),m,mn); nsingle(mn,Sn); isingle(m,IH##k,Si); }
                pf Sn = 0ull, Si = 0ull;
                TREE_BODY2
                float S0n,S1n,S0i,S1i; UPK(Sn,S0n,S1n); UPK(Si,S0i,S1i);
                float w0,w1; UPK(RW(3,3), w0, w1);
#undef TERMP
#undef TERMS
#undef RW
                float c00 = w0 * IL2E, c01 = w1 * IL2E;
                int sy = 2*p;
                sS[0][sy*SSP + x]     = sigm10(c00*S0n, 0.5f);
                sS[0][(sy+1)*SSP + x] = sigm10(c01*S1n, 0.5f);
                sS[1][sy*SSP + x]     = sigm10((vmax - c00)*S0i, 0.5f);
                sS[1][(sy+1)*SSP + x] = sigm10((vmax - c01)*S1i, 0.5f);
            }
            __syncthreads();

            for (int idx = tid, j = 0; idx < 2048; idx += NT, ++j){
                int v = idx >> 10, r = idx & 1023;
                int ly = r >> 5, lx = r & 31;
                float acc = 0.f;
#pragma unroll
                for (int dy = 0; dy < 3; ++dy)
#pragma unroll
                    for (int dx = 0; dx < 3; ++dx)
                        acc += sS[v][(ly+dy)*SSP + lx + dx];
                acc = fminf(fmaxf(acc, 0.f), 1.f);
                cp[ts][j >> 2][j & 3] = acc;
            }
            __syncthreads();
        }

        float local = 0.f;
#pragma unroll
        for (int v = 0; v < 2; ++v)
#pragma unroll
        for (int q = 0; q < 4; ++q){
            float d = cp[0][v][q] - cp[1][v][q];
            local += d*d;
        }
#pragma unroll
        for (int o = 16; o > 0; o >>= 1) local += __shfl_xor_sync(0xffffffffu, local, o);
        if ((tid & 31) == 0) sW[tid >> 5] = local;
        __syncthreads();
        if (tid == 0){
            float s = sW[0];
#pragma unroll
            for (int i = 1; i < 8; ++i) s += sW[i];
            g_partial[bid] = s;
        }
    } else {
        const int e  = bid - 4704;
        const int z  = e / 60;
        const int t  = e - z*60;
        const int pt = z >> 3;
        const int b  = z & 7;
        const int level = pt >> 1;
        const int inv   = pt & 1;
        int bx, by;
        if      (t < 16){ bx = t;      by = 0;      }
        else if (t < 32){ bx = t - 16; by = 15;     }
        else if (t < 46){ bx = 0;      by = t - 31; }
        else            { bx = 15;     by = t - 45; }
        const int oy = by * TS, ox = bx * TS;

        float cp[2][4];
        for (int ts = 0; ts < 2; ++ts){
            const float* base = (ts == 0)
                ? (level == 0 ? pred0 : (level == 1 ? g_pe1 : g_pe2))
                : (level == 0 ? gt0   : (level == 1 ? g_ge1 : g_ge2));
            const float* src = base + b*NPIX;
            float vmax = inv ? __int_as_float(g_vmax[(ts ? 3 : 0) + level]) : 0.f;

            float* A = (float*)fA; float* B = (float*)fB;
            for (int i = tid; i < 39*39; i += NT){
                int a = i / 39, c = i - a*39;
                int qy = oy - 4 + a, qx = ox - 4 + c;
                float v;
                if (qy < -1 || qy > HW || qx < -1 || qx > HW) v = 0.f;
                else if (qy == -1 || qy == HW || qx == -1 || qx == HW) v = L2E;
                else { float u = src[qy*HW + qx]; v = (inv ? vmax - u : u) * L2E; }
                A[(c*PK + (a >> 1))*2 + (a & 1)] = v;
                if (a & 1)       B[(c*PK + (a >> 1))*2]         = v;
                else if (a >= 2) B[(c*PK + (a >> 1) - 1)*2 + 1] = v;
            }
            __syncthreads();

            for (int idx = tid; idx < 34*17; idx += NT){
                int p = idx / 34, x = idx - p*34;
#define RW(r,c) ( ((r) & 1) ? fB[(x+(c))*PK + p + ((r)>>1)] : fA[(x+(c))*PK + p + ((r)>>1)] )
#define TERMP(eA,eB,k) { pf mA,mnA,mB,mnB; mexp((eA),mA,mnA); mexp((eB),mB,mnB); \
                         npair(mnA,mnB,Sn); }
#define TERMS(e,k)     { pf m,mn; mexp((e),m,mn); nsingle(mn,Sn); }
                pf Sn = 0ull;
                TREE_BODY2
                float S0,S1; UPK(Sn,S0,S1);
                float w0,w1; UPK(RW(3,3), w0, w1);
#undef TERMP
#undef TERMS
#undef RW
                float c00 = w0 * IL2E, c01 = w1 * IL2E;
                int sy = 2*p;
                int gy0 = oy + sy - 1, gx = ox + x - 1;
                float s0 = sigm10(c00*S0, 0.5f);
                float s1 = sigm10(c01*S1, 0.5f);
                bool okx = ((unsigned)gx < HW);
                if (!okx || (unsigned)gy0     >= HW) s0 = 0.f;
                if (!okx || (unsigned)(gy0+1) >= HW) s1 = 0.f;
                sS[0][sy*SSP + x]     = s0;
                sS[0][(sy+1)*SSP + x] = s1;
            }
            __syncthreads();

#pragma unroll
            for (int q = 0; q < 4; ++q){
                int ly = (tid >> 5) + q*8, lx = tid & 31;
                float acc = 0.f;
#pragma unroll
                for (int dy = 0; dy < 3; ++dy)
#pragma unroll
                    for (int dx = 0; dx < 3; ++dx)
                        acc += sS[0][(ly+dy)*SSP + lx + dx];
                cp[ts][q] = fminf(fmaxf(acc, 0.f), 1.f);
            }
            __syncthreads();
        }

        float local = 0.f;
#pragma unroll
        for (int q = 0; q < 4; ++q){
            float d = cp[0][q] - cp[1][q];
            local += d*d;
        }
#pragma unroll
        for (int o = 16; o > 0; o >>= 1) local += __shfl_xor_sync(0xffffffffu, local, o);
        if ((tid & 31) == 0) sW[tid >> 5] = local;
        __syncthreads();
        if (tid == 0){
            float s = sW[0];
#pragma unroll
            for (int i = 1; i < 8; ++i) s += sW[i];
            g_partial[bid] = s;
        }
    }
}

// ---------------- deterministic final reduction ----------------
__global__ __launch_bounds__(256) void final_kernel(float* out){
    __shared__ double sh[256];
    double a = 0.0;
    for (int i = threadIdx.x; i < 7584; i += 256) a += (double)g_partial[i];
    sh[threadIdx.x] = a; __syncthreads();
    for (int o = 128; o > 0; o >>= 1){
        if (threadIdx.x < o) sh[threadIdx.x] += sh[threadIdx.x+o];
        __syncthreads();
    }
    if (threadIdx.x == 0) out[0] = (float)(sh[0] * 0.125);
}

// ---------------- launch ----------------
extern "C" void kernel_launch(void* const* d_in, const int* in_sizes, int n_in,
                              void* d_out, int out_size){
    const float* pred = (const float*)d_in[0];
    const float* gt   = (const float*)d_in[1];
    float* out = (float*)d_out;
    (void)in_sizes; (void)n_in; (void)out_size;

    init_kernel<<<1, 32>>>();
    erode_max<1>   <<<dim3(64, 16), 256>>>(pred, gt);
    erode_finish<1><<<dim3(64, 16), 256>>>(pred, gt);
    erode_max<2>   <<<dim3(64, 16), 256>>>(pred, gt);
    erode_finish<2><<<dim3(64, 16), 256>>>(pred, gt);
    cp_all_kernel<<<7584, NT>>>(pred, gt);
    final_kernel<<<1, 256>>>(out);
}